// round 17
// baseline (speedup 1.0000x reference)
#include <cuda_runtime.h>
#include <cuda_bf16.h>

#define NCAM 16

// Champion R4 body + per-block camera rotation: block b starts its camera
// loop at camera (b & 15), so concurrently-running blocks write into all 16
// output regions simultaneously instead of phase-marching through them in
// lockstep -> better HBM bank/channel-level parallelism for the 256MB
// write stream. Everything else is byte-identical to the 43.07us champion.

// ---------- f32x2 packed-math helpers (sm_103a) ----------
__device__ __forceinline__ unsigned long long pk2(float a, float b) {
    unsigned long long r;
    asm("mov.b64 %0, {%1, %2};" : "=l"(r) : "f"(a), "f"(b));
    return r;
}
__device__ __forceinline__ void upk2(unsigned long long v, float& a, float& b) {
    asm("mov.b64 {%0, %1}, %2;" : "=f"(a), "=f"(b) : "l"(v));
}
__device__ __forceinline__ unsigned long long fma2(unsigned long long a,
                                                   unsigned long long b,
                                                   unsigned long long c) {
    unsigned long long d;
    asm("fma.rn.f32x2 %0, %1, %2, %3;" : "=l"(d) : "l"(a), "l"(b), "l"(c));
    return d;
}
__device__ __forceinline__ unsigned long long mul2(unsigned long long a,
                                                   unsigned long long b) {
    unsigned long long d;
    asm("mul.rn.f32x2 %0, %1, %2;" : "=l"(d) : "l"(a), "l"(b));
    return d;
}
__device__ __forceinline__ float frcp(float x) {
    float r;
    asm("rcp.approx.f32 %0, %1;" : "=f"(r) : "f"(x));
    return r;
}

// Shared param layout per camera: 16 duplicated (v,v) pairs (128 B):
//   k 0..8 : r00 r01 r02 r10 r11 r12 r20 r21 r22
//   k 9..11: t0 t1 t2    k 12,13: f0 f1    k 14,15: c0 c1

__global__ __launch_bounds__(256, 5)
void Projection_19713899889207_kernel(
    const float* __restrict__ pt3d,   // (3, Np) SoA
    const float* __restrict__ R,      // (NC, 3, 3)
    const float* __restrict__ t,      // (NC, 3)
    const float* __restrict__ f,      // (NC, 2)
    const float* __restrict__ c,      // (NC, 2)
    float* __restrict__ out,          // (NC*Np, 2)
    int np)
{
    __shared__ __align__(16) float sp[NCAM * 32];

    const int tid = threadIdx.x;
    // stage 512 floats with 256 threads (2 each)
    #pragma unroll
    for (int s = tid; s < NCAM * 32; s += 256) {
        const int cam = s >> 5;
        const int k   = (s & 31) >> 1;
        float v;
        if (k < 9)       v = R[cam * 9 + k];
        else if (k < 12) v = t[cam * 3 + (k - 9)];
        else if (k < 14) v = f[cam * 2 + (k - 12)];
        else             v = c[cam * 2 + (k - 14)];
        sp[s] = v;
    }
    __syncthreads();

    const int i = blockIdx.x * blockDim.x + tid;   // index of a PAIR of points
    const int np2 = np >> 1;
    if (i >= np2) return;

    const unsigned long long x01 =
        __ldg(reinterpret_cast<const unsigned long long*>(pt3d) + i);
    const unsigned long long y01 =
        __ldg(reinterpret_cast<const unsigned long long*>(pt3d + (size_t)np) + i);
    const unsigned long long z01 =
        __ldg(reinterpret_cast<const unsigned long long*>(pt3d + 2 * (size_t)np) + i);

    // Per-block camera rotation (uniform within block -> UR math).
    const int camStart = blockIdx.x & (NCAM - 1);
    // Base output pointer for this pair; per-camera byte offset fits in u32
    // (max 15 * np*8 = 240MB < 4GB).
    char* obase = reinterpret_cast<char*>(out) + (size_t)i * 16;
    const unsigned cam_stride = (unsigned)np * 8u;

    #pragma unroll 1
    for (int k = 0; k < NCAM; ++k) {
        const int cam = (k + camStart) & (NCAM - 1);

        const ulonglong2* Q = reinterpret_cast<const ulonglong2*>(sp + cam * 32);
        const ulonglong2 q0 = Q[0];  // (r00d, r01d)
        const ulonglong2 q1 = Q[1];  // (r02d, r10d)
        const ulonglong2 q2 = Q[2];  // (r11d, r12d)
        const ulonglong2 q3 = Q[3];  // (r20d, r21d)
        const ulonglong2 q4 = Q[4];  // (r22d, t0d)
        const ulonglong2 q5 = Q[5];  // (t1d,  t2d)
        const ulonglong2 q6 = Q[6];  // (f0d,  f1d)
        const ulonglong2 q7 = Q[7];  // (c0d,  c1d)

        const unsigned long long X =
            fma2(q0.x, x01, fma2(q0.y, y01, fma2(q1.x, z01, q4.y)));
        const unsigned long long Y =
            fma2(q1.y, x01, fma2(q2.x, y01, fma2(q2.y, z01, q5.x)));
        const unsigned long long Z =
            fma2(q3.x, x01, fma2(q3.y, y01, fma2(q4.x, z01, q5.y)));

        float z0, z1;
        upk2(Z, z0, z1);
        const unsigned long long IZ = pk2(frcp(z0), frcp(z1));

        const unsigned long long U = fma2(mul2(X, IZ), q6.x, q7.x);
        const unsigned long long V = fma2(mul2(Y, IZ), q6.y, q7.y);

        float u0, u1, v0, v1;
        upk2(U, u0, u1);
        upk2(V, v0, v1);

        // streaming store (.cs evict-first is load-bearing — R12 regression)
        __stcs(reinterpret_cast<float4*>(obase + (size_t)((unsigned)cam * cam_stride)),
               make_float4(u0, v0, u1, v1));
    }
}

extern "C" void kernel_launch(void* const* d_in, const int* in_sizes, int n_in,
                              void* d_out, int out_size)
{
    // metadata order: pt3d (3,Np) f32, R (16,3,3) f32, t (16,3) f32,
    //                 f (16,2) f32, c (16,2) f32, mask (16,Np) i32 (unused)
    const float* pt3d = (const float*)d_in[0];
    const float* R    = (const float*)d_in[1];
    const float* t    = (const float*)d_in[2];
    const float* f    = (const float*)d_in[3];
    const float* c    = (const float*)d_in[4];
    float* out        = (float*)d_out;

    const int np  = in_sizes[0] / 3;        // 2,000,000
    const int np2 = np / 2;
    const int threads = 256;
    const int blocks  = (np2 + threads - 1) / threads;

    Projection_19713899889207_kernel<<<blocks, threads>>>(pt3d, R, t, f, c, out, np);
}